// round 1
// baseline (speedup 1.0000x reference)
#include <cuda_runtime.h>
#include <cuda_bf16.h>
#include <cstdint>

// ---------------- problem constants ----------------
#define T_STEPS 512
#define BATCH   512
#define INSZ    300
#define HID     16
#define NG      64              // 4*HID gates
#define KPAD    304             // 300 padded to 16
#define KSTEPS  19              // 304/16
#define MBLK    256             // rows per GEMM block
#define KSC     10              // ksteps per smem chunk (chunks: 10, 9)

// ---------------- device scratch (no allocs allowed) ----------------
__device__ float d_xg[(size_t)T_STEPS * BATCH * NG];   // [t*B+b][64] fp32
__device__ uint2 d_wph[NG * KSTEPS * 4];               // W_ih hi, B-fragment permuted
__device__ uint2 d_wpl[NG * KSTEPS * 4];               // W_ih lo
__device__ float d_bias[NG];                           // b_ih + b_hh

// ---------------- helpers ----------------
__device__ __forceinline__ uint32_t pack_bf2(float lo_e, float hi_e) {
    __nv_bfloat162 p = __floats2bfloat162_rn(lo_e, hi_e);  // .x = lo_e (low half)
    return *reinterpret_cast<uint32_t*>(&p);
}

__device__ __forceinline__ float sigf(float x) {
    float e = __expf(-x);
    return __fdividef(1.0f, 1.0f + e);
}
__device__ __forceinline__ float tanhfast(float x) {
    float a = fabsf(x);
    float e = __expf(-2.0f * a);
    float t = __fdividef(1.0f - e, 1.0f + e);
    return copysignf(t, x);
}

__device__ __forceinline__ void mma16816(float* d, uint4 a, uint2 b) {
    asm volatile(
        "mma.sync.aligned.m16n8k16.row.col.f32.bf16.bf16.f32 "
        "{%0,%1,%2,%3}, {%4,%5,%6,%7}, {%8,%9}, {%0,%1,%2,%3};"
        : "+f"(d[0]), "+f"(d[1]), "+f"(d[2]), "+f"(d[3])
        : "r"(a.x), "r"(a.y), "r"(a.z), "r"(a.w), "r"(b.x), "r"(b.y));
}

// ---------------- kernel 0: prep W_ih -> permuted bf16 hi/lo, bias ----------------
__global__ void prep_kernel(const float* __restrict__ W_ih,
                            const float* __restrict__ b_ih,
                            const float* __restrict__ b_hh) {
    for (int i = threadIdx.x; i < NG * KSTEPS * 4; i += blockDim.x) {
        int n  = i / (KSTEPS * 4);
        int r  = i % (KSTEPS * 4);
        int ks = r >> 2;
        int t  = r & 3;
        int kw0 = ks * 8 + t;       // word index (k-pair) for b0
        int kw1 = kw0 + 4;          // word index for b1
        float v[4];
        int kk[4] = {2 * kw0, 2 * kw0 + 1, 2 * kw1, 2 * kw1 + 1};
#pragma unroll
        for (int j = 0; j < 4; j++)
            v[j] = (kk[j] < INSZ) ? W_ih[(size_t)n * INSZ + kk[j]] : 0.0f;
        float hi[4], lo[4];
#pragma unroll
        for (int j = 0; j < 4; j++) {
            __nv_bfloat16 h = __float2bfloat16(v[j]);
            hi[j] = __bfloat162float(h);
            lo[j] = v[j] - hi[j];
        }
        d_wph[i] = make_uint2(pack_bf2(hi[0], hi[1]), pack_bf2(hi[2], hi[3]));
        d_wpl[i] = make_uint2(pack_bf2(lo[0], lo[1]), pack_bf2(lo[2], lo[3]));
    }
    if (threadIdx.x < NG)
        d_bias[threadIdx.x] = b_ih[threadIdx.x] + b_hh[threadIdx.x];
}

// ---------------- kernel 1: xg = x @ W_ih^T + bias (bf16-split MMA) ----------------
__global__ void __launch_bounds__(256, 1)
gemm_kernel(const float* __restrict__ x) {
    extern __shared__ __nv_bfloat16 smem[];
    // sA_hi: [16 rowtiles][KSC ksteps][32 lanes] x uint4 (8 bf16) = 40960 bf16
    __nv_bfloat16* sA_hi = smem;
    __nv_bfloat16* sA_lo = smem + 16 * KSC * 32 * 8;

    const int tid  = threadIdx.x;
    const int w    = tid >> 5;
    const int lane = tid & 31;
    const int wm   = w >> 1;          // 0..3 -> rowtiles wm*4 .. wm*4+3 (m64)
    const int wn   = (w & 1) * 32;    // n-half
    const int row0 = blockIdx.x * MBLK;

    float acc[4][4][4];
#pragma unroll
    for (int i = 0; i < 4; i++)
#pragma unroll
        for (int j = 0; j < 4; j++)
#pragma unroll
            for (int r = 0; r < 4; r++) acc[i][j][r] = 0.0f;

    for (int chunk = 0; chunk < 2; chunk++) {
        const int ks0 = chunk * KSC;
        const int nks = chunk ? (KSTEPS - KSC) : KSC;
        if (chunk) __syncthreads();

        // ---- convert x rows -> A-fragment-permuted bf16 hi/lo in smem ----
        const int nelem = MBLK * nks * 16;
        const int kspan = nks * 16;
        for (int idx = tid; idx < nelem; idx += 256) {
            int r    = idx / kspan;
            int kk_c = idx - r * kspan;
            int k    = ks0 * 16 + kk_c;
            float v  = (k < INSZ) ? x[(size_t)(row0 + r) * INSZ + k] : 0.0f;
            __nv_bfloat16 hb = __float2bfloat16(v);
            float lov = v - __bfloat162float(hb);
            __nv_bfloat16 lb = __float2bfloat16(lov);
            int ksl = kk_c >> 4;
            int kk  = kk_c & 15;
            int rt  = r >> 4;
            int rr  = r & 15;
            int ln   = (rr & 7) * 4 + ((kk & 7) >> 1);
            int wsel = ((kk >> 3) << 1) | (rr >> 3);   // a0:(rlo,klo) a1:(rhi,klo) a2:(rlo,khi) a3:(rhi,khi)
            int off  = (((rt * KSC + ksl) * 32 + ln) << 3) + (wsel << 1) + (kk & 1);
            sA_hi[off] = hb;
            sA_lo[off] = lb;
        }
        __syncthreads();

        // ---- MMA mainloop: 3 passes (hi*hi, hi*lo, lo*hi) ----
        for (int pass = 0; pass < 3; pass++) {
            const __nv_bfloat16* As = (pass == 2) ? sA_lo : sA_hi;
            const uint2* Wp = (pass == 1) ? d_wpl : d_wph;
            for (int ksl = 0; ksl < nks; ksl++) {
                const int ksg = ks0 + ksl;
                uint4 a[4];
#pragma unroll
                for (int i = 0; i < 4; i++) {
                    int rt = wm * 4 + i;
                    a[i] = *reinterpret_cast<const uint4*>(
                        As + (((rt * KSC + ksl) * 32 + lane) << 3));
                }
#pragma unroll
                for (int j = 0; j < 4; j++) {
                    int n = wn + j * 8 + (lane >> 2);
                    uint2 b = Wp[(n * KSTEPS + ksg) * 4 + (lane & 3)];
#pragma unroll
                    for (int i = 0; i < 4; i++) mma16816(acc[i][j], a[i], b);
                }
            }
        }
    }

    // ---- epilogue: add bias, store fp32 ----
    const int cr  = lane >> 2;
    const int cc2 = (lane & 3) * 2;
#pragma unroll
    for (int i = 0; i < 4; i++) {
#pragma unroll
        for (int j = 0; j < 4; j++) {
            int col = wn + j * 8 + cc2;
            float b0 = d_bias[col], b1v = d_bias[col + 1];
            int rA = row0 + wm * 64 + i * 16 + cr;
            float2 v0 = make_float2(acc[i][j][0] + b0, acc[i][j][1] + b1v);
            *reinterpret_cast<float2*>(&d_xg[(size_t)rA * NG + col]) = v0;
            float2 v1 = make_float2(acc[i][j][2] + b0, acc[i][j][3] + b1v);
            *reinterpret_cast<float2*>(&d_xg[(size_t)(rA + 8) * NG + col]) = v1;
        }
    }
}

// ---------------- kernel 2: LSTM scan (warp per batch elem) + fused MLP head ----------------
__global__ void __launch_bounds__(128)
scan_kernel(const float* __restrict__ Whh,
            const float* __restrict__ W1, const float* __restrict__ b1,
            const float* __restrict__ W2, const float* __restrict__ b2,
            float* __restrict__ out) {
    const int warp = threadIdx.x >> 5;
    const int lane = threadIdx.x & 31;
    const int b    = blockIdx.x * 4 + warp;
    const int l    = lane & 15;
    const unsigned FULL = 0xffffffffu;

    // lane computes gates (lane) and (lane+32)
    float w1r[HID], w2r[HID];
#pragma unroll
    for (int k = 0; k < HID; k++) {
        w1r[k] = Whh[lane * HID + k];
        w2r[k] = Whh[(lane + 32) * HID + k];
    }

    float h = 0.0f, c = 0.0f;

    // prefetch ring, depth 4
    float xa[4], xb[4];
#pragma unroll
    for (int p = 0; p < 4; p++) {
        size_t off = ((size_t)p * BATCH + b) * NG;
        xa[p] = d_xg[off + lane];
        xb[p] = d_xg[off + 32 + lane];
    }

    for (int t = 0; t < T_STEPS; t++) {
        const int s = t & 3;
        float g1 = xa[s];
        float g2 = xb[s];
        if (t + 4 < T_STEPS) {
            size_t off = ((size_t)(t + 4) * BATCH + b) * NG;
            xa[s] = d_xg[off + lane];
            xb[s] = d_xg[off + 32 + lane];
        }
        // gates += h @ Whh^T  (split accumulation to shorten chains)
        float g1b = 0.0f, g2b = 0.0f;
#pragma unroll
        for (int k = 0; k < 8; k++) {
            float hk = __shfl_sync(FULL, h, k);
            g1  = fmaf(hk, w1r[k], g1);
            g2  = fmaf(hk, w2r[k], g2);
        }
#pragma unroll
        for (int k = 8; k < HID; k++) {
            float hk = __shfl_sync(FULL, h, k);
            g1b = fmaf(hk, w1r[k], g1b);
            g2b = fmaf(hk, w2r[k], g2b);
        }
        g1 += g1b;
        g2 += g2b;

        // lane l (<16): i = g1(l), f = g1(l+16), g = g2(l), o = g2(l+16)
        float fg = __shfl_sync(FULL, g1, l + 16);
        float og = __shfl_sync(FULL, g2, l + 16);
        float i_s = sigf(g1);
        float f_s = sigf(fg);
        float g_t = tanhfast(g2);
        c = f_s * c + i_s * g_t;
        h = sigf(og) * tanhfast(c);
    }

    // ---- fused MLP head: out[b] = 4*sigmoid(relu(h@W1^T+b1) @ W2^T + b2) ----
    float wa[HID], wb[HID];
#pragma unroll
    for (int k = 0; k < HID; k++) {
        wa[k] = W1[lane * HID + k];
        wb[k] = W1[(lane + 32) * HID + k];
    }
    float za = b1[lane], zb = b1[lane + 32];
#pragma unroll
    for (int k = 0; k < HID; k++) {
        float hk = __shfl_sync(FULL, h, k);
        za = fmaf(hk, wa[k], za);
        zb = fmaf(hk, wb[k], zb);
    }
    za = fmaxf(za, 0.0f);
    zb = fmaxf(zb, 0.0f);
    float sacc = za * W2[lane] + zb * W2[lane + 32];
#pragma unroll
    for (int off = 16; off > 0; off >>= 1)
        sacc += __shfl_xor_sync(FULL, sacc, off);
    if (lane == 0) out[b] = 4.0f * sigf(sacc + b2[0]);
}

// ---------------- launch ----------------
extern "C" void kernel_launch(void* const* d_in, const int* in_sizes, int n_in,
                              void* d_out, int out_size) {
    const float* x    = (const float*)d_in[0];
    const float* W_ih = (const float*)d_in[1];
    const float* W_hh = (const float*)d_in[2];
    const float* b_ih = (const float*)d_in[3];
    const float* b_hh = (const float*)d_in[4];
    const float* W1   = (const float*)d_in[5];
    const float* b1   = (const float*)d_in[6];
    const float* W2   = (const float*)d_in[7];
    const float* b2   = (const float*)d_in[8];
    float* out = (float*)d_out;

    const int smem_bytes = 2 * 16 * KSC * 32 * 8 * (int)sizeof(__nv_bfloat16); // 163840
    cudaFuncSetAttribute(gemm_kernel, cudaFuncAttributeMaxDynamicSharedMemorySize, smem_bytes);

    prep_kernel<<<1, 256>>>(W_ih, b_ih, b_hh);
    gemm_kernel<<<(T_STEPS * BATCH) / MBLK, 256, smem_bytes>>>(x);
    scan_kernel<<<BATCH / 4, 128>>>(W_hh, W1, b1, W2, b2, out);
}

// round 2
// speedup vs baseline: 1.0224x; 1.0224x over previous
#include <cuda_runtime.h>
#include <cuda_bf16.h>
#include <cstdint>

// ---------------- problem constants ----------------
#define T_STEPS 512
#define BATCH   512
#define INSZ    300
#define HID     16
#define NG      64              // 4*HID gates
#define KPAD    304             // 300 padded to 16
#define KSTEPS  19              // 304/16
#define MBLK    256             // rows per GEMM block
#define KSC     10              // ksteps per smem chunk (chunks: 10, 9)

// ---------------- device scratch (no allocs allowed) ----------------
__device__ float d_xg[(size_t)T_STEPS * BATCH * NG];   // [t*B+b][64] fp32
__device__ uint2 d_wph[NG * KSTEPS * 4];               // W_ih hi, B-fragment permuted
__device__ uint2 d_wpl[NG * KSTEPS * 4];               // W_ih lo
__device__ float d_bias[NG];                           // b_ih + b_hh

// ---------------- helpers ----------------
__device__ __forceinline__ uint32_t pack_bf2(float lo_e, float hi_e) {
    __nv_bfloat162 p = __floats2bfloat162_rn(lo_e, hi_e);  // .x = lo_e (low half)
    return *reinterpret_cast<uint32_t*>(&p);
}

__device__ __forceinline__ float sigf(float x) {
    float e = __expf(-x);
    return __fdividef(1.0f, 1.0f + e);
}
__device__ __forceinline__ float tanhfast(float x) {
    float a = fabsf(x);
    float e = __expf(-2.0f * a);
    float t = __fdividef(1.0f - e, 1.0f + e);
    return copysignf(t, x);
}

__device__ __forceinline__ void mma16816(float* d, uint4 a, uint2 b) {
    asm volatile(
        "mma.sync.aligned.m16n8k16.row.col.f32.bf16.bf16.f32 "
        "{%0,%1,%2,%3}, {%4,%5,%6,%7}, {%8,%9}, {%0,%1,%2,%3};"
        : "+f"(d[0]), "+f"(d[1]), "+f"(d[2]), "+f"(d[3])
        : "r"(a.x), "r"(a.y), "r"(a.z), "r"(a.w), "r"(b.x), "r"(b.y));
}

// ---------------- kernel 0: prep W_ih -> permuted bf16 hi/lo, bias ----------------
__global__ void prep_kernel(const float* __restrict__ W_ih,
                            const float* __restrict__ b_ih,
                            const float* __restrict__ b_hh) {
    for (int i = threadIdx.x; i < NG * KSTEPS * 4; i += blockDim.x) {
        int n  = i / (KSTEPS * 4);
        int r  = i % (KSTEPS * 4);
        int ks = r >> 2;
        int t  = r & 3;
        int kw0 = ks * 8 + t;       // word index (k-pair) for b0
        int kw1 = kw0 + 4;          // word index for b1
        float v[4];
        int kk[4] = {2 * kw0, 2 * kw0 + 1, 2 * kw1, 2 * kw1 + 1};
#pragma unroll
        for (int j = 0; j < 4; j++)
            v[j] = (kk[j] < INSZ) ? W_ih[(size_t)n * INSZ + kk[j]] : 0.0f;
        float hi[4], lo[4];
#pragma unroll
        for (int j = 0; j < 4; j++) {
            __nv_bfloat16 h = __float2bfloat16(v[j]);
            hi[j] = __bfloat162float(h);
            lo[j] = v[j] - hi[j];
        }
        d_wph[i] = make_uint2(pack_bf2(hi[0], hi[1]), pack_bf2(hi[2], hi[3]));
        d_wpl[i] = make_uint2(pack_bf2(lo[0], lo[1]), pack_bf2(lo[2], lo[3]));
    }
    if (threadIdx.x < NG)
        d_bias[threadIdx.x] = b_ih[threadIdx.x] + b_hh[threadIdx.x];
}

// ---------------- kernel 1: xg = x @ W_ih^T + bias (bf16-split MMA) ----------------
__global__ void __launch_bounds__(256, 1)
gemm_kernel(const float* __restrict__ x) {
    extern __shared__ __nv_bfloat16 smem[];
    // sA_hi: [16 rowtiles][KSC ksteps][32 lanes] x uint4 (8 bf16) = 40960 bf16
    __nv_bfloat16* sA_hi = smem;
    __nv_bfloat16* sA_lo = smem + 16 * KSC * 32 * 8;

    const int tid  = threadIdx.x;
    const int w    = tid >> 5;
    const int lane = tid & 31;
    const int wm   = w >> 1;          // 0..3 -> rowtiles wm*4 .. wm*4+3 (m64)
    const int wn   = (w & 1) * 32;    // n-half
    const int row0 = blockIdx.x * MBLK;

    float acc[4][4][4];
#pragma unroll
    for (int i = 0; i < 4; i++)
#pragma unroll
        for (int j = 0; j < 4; j++)
#pragma unroll
            for (int r = 0; r < 4; r++) acc[i][j][r] = 0.0f;

    for (int chunk = 0; chunk < 2; chunk++) {
        const int ks0 = chunk * KSC;
        const int nks = chunk ? (KSTEPS - KSC) : KSC;
        if (chunk) __syncthreads();

        // ---- convert x rows -> A-fragment-permuted bf16 hi/lo in smem ----
        const int nelem = MBLK * nks * 16;
        const int kspan = nks * 16;
        for (int idx = tid; idx < nelem; idx += 256) {
            int r    = idx / kspan;
            int kk_c = idx - r * kspan;
            int k    = ks0 * 16 + kk_c;
            float v  = (k < INSZ) ? x[(size_t)(row0 + r) * INSZ + k] : 0.0f;
            __nv_bfloat16 hb = __float2bfloat16(v);
            float lov = v - __bfloat162float(hb);
            __nv_bfloat16 lb = __float2bfloat16(lov);
            int ksl = kk_c >> 4;
            int kk  = kk_c & 15;
            int rt  = r >> 4;
            int rr  = r & 15;
            int ln   = (rr & 7) * 4 + ((kk & 7) >> 1);
            int wsel = ((kk >> 3) << 1) | (rr >> 3);   // a0:(rlo,klo) a1:(rhi,klo) a2:(rlo,khi) a3:(rhi,khi)
            int off  = (((rt * KSC + ksl) * 32 + ln) << 3) + (wsel << 1) + (kk & 1);
            sA_hi[off] = hb;
            sA_lo[off] = lb;
        }
        __syncthreads();

        // ---- MMA mainloop: 3 passes (hi*hi, hi*lo, lo*hi) ----
        for (int pass = 0; pass < 3; pass++) {
            const __nv_bfloat16* As = (pass == 2) ? sA_lo : sA_hi;
            const uint2* Wp = (pass == 1) ? d_wpl : d_wph;
            for (int ksl = 0; ksl < nks; ksl++) {
                const int ksg = ks0 + ksl;
                uint4 a[4];
#pragma unroll
                for (int i = 0; i < 4; i++) {
                    int rt = wm * 4 + i;
                    a[i] = *reinterpret_cast<const uint4*>(
                        As + (((rt * KSC + ksl) * 32 + lane) << 3));
                }
#pragma unroll
                for (int j = 0; j < 4; j++) {
                    int n = wn + j * 8 + (lane >> 2);
                    uint2 b = Wp[(n * KSTEPS + ksg) * 4 + (lane & 3)];
#pragma unroll
                    for (int i = 0; i < 4; i++) mma16816(acc[i][j], a[i], b);
                }
            }
        }
    }

    // ---- epilogue: add bias, store fp32 ----
    const int cr  = lane >> 2;
    const int cc2 = (lane & 3) * 2;
#pragma unroll
    for (int i = 0; i < 4; i++) {
#pragma unroll
        for (int j = 0; j < 4; j++) {
            int col = wn + j * 8 + cc2;
            float b0 = d_bias[col], b1v = d_bias[col + 1];
            int rA = row0 + wm * 64 + i * 16 + cr;
            float2 v0 = make_float2(acc[i][j][0] + b0, acc[i][j][1] + b1v);
            *reinterpret_cast<float2*>(&d_xg[(size_t)rA * NG + col]) = v0;
            float2 v1 = make_float2(acc[i][j][2] + b0, acc[i][j][3] + b1v);
            *reinterpret_cast<float2*>(&d_xg[(size_t)(rA + 8) * NG + col]) = v1;
        }
    }
}

// ---------------- kernel 2: LSTM scan (warp per batch elem) + fused MLP head ----------------
__global__ void __launch_bounds__(128)
scan_kernel(const float* __restrict__ Whh,
            const float* __restrict__ W1, const float* __restrict__ b1,
            const float* __restrict__ W2, const float* __restrict__ b2,
            float* __restrict__ out) {
    const int warp = threadIdx.x >> 5;
    const int lane = threadIdx.x & 31;
    const int b    = blockIdx.x * 4 + warp;
    const int l    = lane & 15;
    const unsigned FULL = 0xffffffffu;

    // lane computes gates (lane) and (lane+32)
    float w1r[HID], w2r[HID];
#pragma unroll
    for (int k = 0; k < HID; k++) {
        w1r[k] = Whh[lane * HID + k];
        w2r[k] = Whh[(lane + 32) * HID + k];
    }

    float h = 0.0f, c = 0.0f;

    // prefetch ring, depth 4
    float xa[4], xb[4];
#pragma unroll
    for (int p = 0; p < 4; p++) {
        size_t off = ((size_t)p * BATCH + b) * NG;
        xa[p] = d_xg[off + lane];
        xb[p] = d_xg[off + 32 + lane];
    }

    for (int t = 0; t < T_STEPS; t++) {
        const int s = t & 3;
        float g1 = xa[s];
        float g2 = xb[s];
        if (t + 4 < T_STEPS) {
            size_t off = ((size_t)(t + 4) * BATCH + b) * NG;
            xa[s] = d_xg[off + lane];
            xb[s] = d_xg[off + 32 + lane];
        }
        // gates += h @ Whh^T  (split accumulation to shorten chains)
        float g1b = 0.0f, g2b = 0.0f;
#pragma unroll
        for (int k = 0; k < 8; k++) {
            float hk = __shfl_sync(FULL, h, k);
            g1  = fmaf(hk, w1r[k], g1);
            g2  = fmaf(hk, w2r[k], g2);
        }
#pragma unroll
        for (int k = 8; k < HID; k++) {
            float hk = __shfl_sync(FULL, h, k);
            g1b = fmaf(hk, w1r[k], g1b);
            g2b = fmaf(hk, w2r[k], g2b);
        }
        g1 += g1b;
        g2 += g2b;

        // lane l (<16): i = g1(l), f = g1(l+16), g = g2(l), o = g2(l+16)
        float fg = __shfl_sync(FULL, g1, l + 16);
        float og = __shfl_sync(FULL, g2, l + 16);
        float i_s = sigf(g1);
        float f_s = sigf(fg);
        float g_t = tanhfast(g2);
        c = f_s * c + i_s * g_t;
        h = sigf(og) * tanhfast(c);
    }

    // ---- fused MLP head: out[b] = 4*sigmoid(relu(h@W1^T+b1) @ W2^T + b2) ----
    float wa[HID], wb[HID];
#pragma unroll
    for (int k = 0; k < HID; k++) {
        wa[k] = W1[lane * HID + k];
        wb[k] = W1[(lane + 32) * HID + k];
    }
    float za = b1[lane], zb = b1[lane + 32];
#pragma unroll
    for (int k = 0; k < HID; k++) {
        float hk = __shfl_sync(FULL, h, k);
        za = fmaf(hk, wa[k], za);
        zb = fmaf(hk, wb[k], zb);
    }
    za = fmaxf(za, 0.0f);
    zb = fmaxf(zb, 0.0f);
    float sacc = za * W2[lane] + zb * W2[lane + 32];
#pragma unroll
    for (int off = 16; off > 0; off >>= 1)
        sacc += __shfl_xor_sync(FULL, sacc, off);
    if (lane == 0) out[b] = 4.0f * sigf(sacc + b2[0]);
}

// ---------------- launch ----------------
extern "C" void kernel_launch(void* const* d_in, const int* in_sizes, int n_in,
                              void* d_out, int out_size) {
    const float* x    = (const float*)d_in[0];
    const float* W_ih = (const float*)d_in[1];
    const float* W_hh = (const float*)d_in[2];
    const float* b_ih = (const float*)d_in[3];
    const float* b_hh = (const float*)d_in[4];
    const float* W1   = (const float*)d_in[5];
    const float* b1   = (const float*)d_in[6];
    const float* W2   = (const float*)d_in[7];
    const float* b2   = (const float*)d_in[8];
    float* out = (float*)d_out;

    const int smem_bytes = 2 * 16 * KSC * 32 * 8 * (int)sizeof(__nv_bfloat16); // 163840
    cudaFuncSetAttribute(gemm_kernel, cudaFuncAttributeMaxDynamicSharedMemorySize, smem_bytes);

    prep_kernel<<<1, 256>>>(W_ih, b_ih, b_hh);
    gemm_kernel<<<(T_STEPS * BATCH) / MBLK, 256, smem_bytes>>>(x);
    scan_kernel<<<BATCH / 4, 128>>>(W_hh, W1, b1, W2, b2, out);
}

// round 4
// speedup vs baseline: 2.9950x; 2.9293x over previous
#include <cuda_runtime.h>
#include <cstdint>

#define T_STEPS 512
#define BATCH   512
#define INSZ    300
#define HID     16
#define NG      64
#define NROWS   (T_STEPS*BATCH)     // 262144
#define TILE_M  256
#define NTILES  (NROWS/TILE_M)      // 1024
#define GRID_G  148
#define KSTEPS  38                  // 304/8

// smem (floats): A0 [256x64], A1 [256x64], B [38][64][4][2]
#define A_ELEMS (TILE_M*64)         // 16384 floats per buffer
#define B_ELEMS (KSTEPS*64*8)       // 19456 floats
#define SMEM_FLOATS (2*A_ELEMS + B_ELEMS)
#define SMEM_BYTES  (SMEM_FLOATS*4) // 208896

__device__ float d_xg[(size_t)NROWS * NG];

// ---------------- asm helpers ----------------
__device__ __forceinline__ uint32_t smem_u32(const void* p) {
    uint32_t a;
    asm("{ .reg .u64 t; cvta.to.shared.u64 t, %1; cvt.u32.u64 %0, t; }" : "=r"(a) : "l"(p));
    return a;
}
__device__ __forceinline__ void cp16(uint32_t sa, const float* g) {
    asm volatile("cp.async.cg.shared.global [%0], [%1], 16;" :: "r"(sa), "l"(g) : "memory");
}
#define CP_COMMIT() asm volatile("cp.async.commit_group;" ::: "memory")
#define CP_WAIT1()  asm volatile("cp.async.wait_group 1;" ::: "memory")

__device__ __forceinline__ void mma8(float* d, uint32_t a0, uint32_t a1, uint32_t a2, uint32_t a3,
                                     uint32_t b0, uint32_t b1) {
    asm volatile(
        "mma.sync.aligned.m16n8k8.row.col.f32.tf32.tf32.f32 "
        "{%0,%1,%2,%3}, {%4,%5,%6,%7}, {%8,%9}, {%0,%1,%2,%3};"
        : "+f"(d[0]), "+f"(d[1]), "+f"(d[2]), "+f"(d[3])
        : "r"(a0), "r"(a1), "r"(a2), "r"(a3), "r"(b0), "r"(b1));
}

// A layout within a chunk buffer (k local 0..63):
//   off(r,k) = r*64 + (((k>>3) ^ (r&7))<<3) + (k&7)
// B layout: off(n,k) = ((k>>3)*64 + n)*8 + ((k&3)<<1) + ((k&7)>>2)

// copy one 64-col K-chunk of a 256-row tile into buffer (cp.async.16)
__device__ __forceinline__ void cp_chunk(const float* __restrict__ x, uint32_t abase,
                                         float* __restrict__ sdst, int tile, int ch) {
    const int tid = threadIdx.x;
    const int rr = tid >> 4;          // 0..7
    const int j  = tid & 15;          // 16B group within 64 cols
    const int c0 = ch * 64;
    const int jmax = (ch == 4) ? 11 : 16;
    const uint32_t koff = (uint32_t)((((j >> 1) & 7) << 3) | ((j & 1) << 2));  // pre-XOR k part
#pragma unroll
    for (int p = 0; p < 32; p++) {
        int r = p * 8 + rr;
        uint32_t soff = abase + (((uint32_t)r << 6) + (koff ^ (((uint32_t)(r & 7)) << 3))) * 4u;
        if (j < jmax) {
            cp16(soff, x + (size_t)(tile * TILE_M + r) * INSZ + c0 + 4 * j);
        } else if (ch == 4 && j == 11) {
            // zero-pad k=300..303 (local k 44..47)
            asm volatile("st.shared.v4.u32 [%0], {%1,%1,%1,%1};" :: "r"(soff), "r"(0u) : "memory");
        }
    }
    CP_COMMIT();
}

// ---------------- GEMM: d_xg = x @ W_ih^T + 0  (tf32 mma.sync, persistent) ----------------
__global__ void __launch_bounds__(128, 1)
gemm_kernel(const float* __restrict__ x, const float* __restrict__ W) {
    extern __shared__ float sm[];
    float* sA0 = sm;
    float* sA1 = sm + A_ELEMS;
    float* sB  = sm + 2 * A_ELEMS;
    const uint32_t sbase = smem_u32(sm);
    const uint32_t aB[2] = { sbase, sbase + A_ELEMS * 4u };
    float* sAp[2] = { sA0, sA1 };

    const int tid  = threadIdx.x;
    const int w    = tid >> 5;
    const int lane = tid & 31;
    const int g    = lane >> 2;       // groupID 0..7
    const int tg   = lane & 3;        // thread-in-group

    // prime chunk0 of first tile into buf0
    cp_chunk(x, aB[0], sA0, blockIdx.x, 0);

    // B fill (once): W[n][k] -> fragment-pair layout; LDG via L2
    for (int i = tid; i < NG * INSZ; i += 128) {
        int n = i / INSZ, k = i - n * INSZ;
        sB[(((k >> 3) * 64 + n) << 3) + ((k & 3) << 1) + ((k & 7) >> 2)] = W[i];
    }
    // zero B tail k=300..303 (s=37, half=1)
    for (int i = tid; i < 256; i += 128) {
        int n = i >> 2, q = i & 3;
        sB[((37 * 64 + n) << 3) + (q << 1) + 1] = 0.0f;
    }
    __syncthreads();

    int buf = 0;
    for (int tile = blockIdx.x; tile < NTILES; tile += GRID_G) {
        float acc[4][8][4];
#pragma unroll
        for (int i = 0; i < 4; i++)
#pragma unroll
            for (int j = 0; j < 8; j++)
#pragma unroll
                for (int r = 0; r < 4; r++) acc[i][j][r] = 0.0f;

        for (int ch = 0; ch < 5; ch++) {
            // issue next chunk into other buffer
            int ntile = tile, nch = ch + 1;
            if (nch == 5) { ntile = tile + GRID_G; nch = 0; }
            if (ntile < NTILES) cp_chunk(x, aB[buf ^ 1], sAp[buf ^ 1], ntile, nch);
            else CP_COMMIT();
            CP_WAIT1();            // current chunk resident
            __syncthreads();

            const uint32_t* A = reinterpret_cast<const uint32_t*>(sAp[buf]);
            const int ks = (ch == 4) ? 6 : 8;
            for (int s = 0; s < ks; s++) {
                // B frags: 8 n-tiles
                uint32_t b0[8], b1[8];
                const uint32_t* Bf = reinterpret_cast<const uint32_t*>(sB)
                                   + ((((ch * 8 + s) * 64) + g) << 3) + (tg << 1);
#pragma unroll
                for (int j = 0; j < 8; j++) {
                    b0[j] = Bf[j * 64];       // n = 8j+g
                    b1[j] = Bf[j * 64 + 1];
                }
#pragma unroll
                for (int i = 0; i < 4; i++) {
                    int r0 = w * 64 + i * 16 + g;
                    uint32_t base0 = ((uint32_t)r0 << 6) + (((uint32_t)(s ^ g)) << 3);
                    uint32_t base1 = base0 + (8u << 6);   // row +8, same (r&7)
                    uint32_t a0 = A[base0 + tg];
                    uint32_t a2 = A[base0 + tg + 4];
                    uint32_t a1 = A[base1 + tg];
                    uint32_t a3 = A[base1 + tg + 4];
#pragma unroll
                    for (int j = 0; j < 8; j++)
                        mma8(acc[i][j], a0, a1, a2, a3, b0[j], b1[j]);
                }
            }
            __syncthreads();       // all reads of buf done before it is overwritten
            buf ^= 1;
        }

        // epilogue: store tile
#pragma unroll
        for (int i = 0; i < 4; i++) {
            int r0 = tile * TILE_M + w * 64 + i * 16 + g;
#pragma unroll
            for (int j = 0; j < 8; j++) {
                int col = j * 8 + tg * 2;
                *reinterpret_cast<float2*>(&d_xg[(size_t)r0 * NG + col]) =
                    make_float2(acc[i][j][0], acc[i][j][1]);
                *reinterpret_cast<float2*>(&d_xg[(size_t)(r0 + 8) * NG + col]) =
                    make_float2(acc[i][j][2], acc[i][j][3]);
            }
        }
    }
}

// ---------------- scan: LSTM recurrence (warp per batch elem) + fused MLP head ----------------
__device__ __forceinline__ float sigf(float x) {
    float e = __expf(-x);
    return __fdividef(1.0f, 1.0f + e);
}
__device__ __forceinline__ float tanhfast(float x) {
    float a = fabsf(x);
    float e = __expf(-2.0f * a);
    float t = __fdividef(1.0f - e, 1.0f + e);
    return copysignf(t, x);
}

__global__ void __launch_bounds__(128)
scan_kernel(const float* __restrict__ Whh,
            const float* __restrict__ b_ih, const float* __restrict__ b_hh,
            const float* __restrict__ W1, const float* __restrict__ b1,
            const float* __restrict__ W2, const float* __restrict__ b2,
            float* __restrict__ out) {
    const int warp = threadIdx.x >> 5;
    const int lane = threadIdx.x & 31;
    const int b = blockIdx.x * 4 + warp;
    const int l = lane & 15;
    const unsigned FULL = 0xffffffffu;

    float w1r[HID], w2r[HID];
#pragma unroll
    for (int k = 0; k < HID; k++) {
        w1r[k] = Whh[lane * HID + k];
        w2r[k] = Whh[(lane + 32) * HID + k];
    }
    const float biasA = b_ih[lane] + b_hh[lane];
    const float biasB = b_ih[lane + 32] + b_hh[lane + 32];

    float h = 0.0f, c = 0.0f;
    float xa[4], xb[4];
#pragma unroll
    for (int p = 0; p < 4; p++) {
        size_t off = ((size_t)p * BATCH + b) * NG;
        xa[p] = d_xg[off + lane];
        xb[p] = d_xg[off + 32 + lane];
    }

    for (int t = 0; t < T_STEPS; t++) {
        const int s = t & 3;
        float g1 = xa[s] + biasA;
        float g2 = xb[s] + biasB;
        if (t + 4 < T_STEPS) {
            size_t off = ((size_t)(t + 4) * BATCH + b) * NG;
            xa[s] = d_xg[off + lane];
            xb[s] = d_xg[off + 32 + lane];
        }
        float g1b = 0.0f, g2b = 0.0f;
#pragma unroll
        for (int k = 0; k < 8; k++) {
            float hk = __shfl_sync(FULL, h, k);
            g1 = fmaf(hk, w1r[k], g1);
            g2 = fmaf(hk, w2r[k], g2);
        }
#pragma unroll
        for (int k = 8; k < HID; k++) {
            float hk = __shfl_sync(FULL, h, k);
            g1b = fmaf(hk, w1r[k], g1b);
            g2b = fmaf(hk, w2r[k], g2b);
        }
        g1 += g1b;
        g2 += g2b;

        float fg = __shfl_sync(FULL, g1, l + 16);
        float og = __shfl_sync(FULL, g2, l + 16);
        float i_s = sigf(g1);
        float f_s = sigf(fg);
        float g_t = tanhfast(g2);
        c = f_s * c + i_s * g_t;
        h = sigf(og) * tanhfast(c);
    }

    float wa[HID], wb[HID];
#pragma unroll
    for (int k = 0; k < HID; k++) {
        wa[k] = W1[lane * HID + k];
        wb[k] = W1[(lane + 32) * HID + k];
    }
    float za = b1[lane], zb = b1[lane + 32];
#pragma unroll
    for (int k = 0; k < HID; k++) {
        float hk = __shfl_sync(FULL, h, k);
        za = fmaf(hk, wa[k], za);
        zb = fmaf(hk, wb[k], zb);
    }
    za = fmaxf(za, 0.0f);
    zb = fmaxf(zb, 0.0f);
    float sacc = za * W2[lane] + zb * W2[lane + 32];
#pragma unroll
    for (int off = 16; off > 0; off >>= 1)
        sacc += __shfl_xor_sync(FULL, sacc, off);
    if (lane == 0) out[b] = 4.0f * sigf(sacc + b2[0]);
}

// ---------------- launch ----------------
extern "C" void kernel_launch(void* const* d_in, const int* in_sizes, int n_in,
                              void* d_out, int out_size) {
    const float* x    = (const float*)d_in[0];
    const float* W_ih = (const float*)d_in[1];
    const float* W_hh = (const float*)d_in[2];
    const float* b_ih = (const float*)d_in[3];
    const float* b_hh = (const float*)d_in[4];
    const float* W1   = (const float*)d_in[5];
    const float* b1   = (const float*)d_in[6];
    const float* W2   = (const float*)d_in[7];
    const float* b2   = (const float*)d_in[8];
    float* out = (float*)d_out;

    cudaFuncSetAttribute(gemm_kernel, cudaFuncAttributeMaxDynamicSharedMemorySize, SMEM_BYTES);
    gemm_kernel<<<GRID_G, 128, SMEM_BYTES>>>(x, W_ih);
    scan_kernel<<<BATCH / 4, 128>>>(W_hh, b_ih, b_hh, W1, b1, W2, b2, out);
}

// round 5
// speedup vs baseline: 4.5951x; 1.5343x over previous
#include <cuda_runtime.h>
#include <cstdint>

#define T_STEPS 512
#define BATCH   512
#define INSZ    300
#define HID     16
#define NG      64
#define NROWS   (T_STEPS*BATCH)     // 262144
#define TILE_M  256
#define NTILES  (NROWS/TILE_M)      // 1024
#define GRID_G  148
#define KSTEPS  38                  // 304/8
#define STRIDE_T (BATCH*NG)         // floats per timestep in d_xg

// smem (floats): A0 [256x64], A1 [256x64], B [38][64][4][2]
#define A_ELEMS (TILE_M*64)         // 16384 floats per buffer
#define B_ELEMS (KSTEPS*64*8)       // 19456 floats
#define SMEM_FLOATS (2*A_ELEMS + B_ELEMS)
#define SMEM_BYTES  (SMEM_FLOATS*4) // 208896

// padded by 4 timesteps so the scan prefetch never reads OOB
__device__ float d_xg[(size_t)(NROWS + 4 * BATCH) * NG];

// ---------------- asm helpers ----------------
__device__ __forceinline__ uint32_t smem_u32(const void* p) {
    uint32_t a;
    asm("{ .reg .u64 t; cvta.to.shared.u64 t, %1; cvt.u32.u64 %0, t; }" : "=r"(a) : "l"(p));
    return a;
}
__device__ __forceinline__ void cp16(uint32_t sa, const float* g) {
    asm volatile("cp.async.cg.shared.global [%0], [%1], 16;" :: "r"(sa), "l"(g) : "memory");
}
#define CP_COMMIT() asm volatile("cp.async.commit_group;" ::: "memory")
#define CP_WAIT1()  asm volatile("cp.async.wait_group 1;" ::: "memory")

__device__ __forceinline__ void mma8(float* d, uint32_t a0, uint32_t a1, uint32_t a2, uint32_t a3,
                                     uint32_t b0, uint32_t b1) {
    asm volatile(
        "mma.sync.aligned.m16n8k8.row.col.f32.tf32.tf32.f32 "
        "{%0,%1,%2,%3}, {%4,%5,%6,%7}, {%8,%9}, {%0,%1,%2,%3};"
        : "+f"(d[0]), "+f"(d[1]), "+f"(d[2]), "+f"(d[3])
        : "r"(a0), "r"(a1), "r"(a2), "r"(a3), "r"(b0), "r"(b1));
}

// copy one 64-col K-chunk of a 256-row tile into buffer (cp.async.16)
__device__ __forceinline__ void cp_chunk(const float* __restrict__ x, uint32_t abase,
                                         int tile, int ch) {
    const int tid = threadIdx.x;
    const int rr = tid >> 4;          // 0..7
    const int j  = tid & 15;          // 16B group within 64 cols
    const int c0 = ch * 64;
    const int jmax = (ch == 4) ? 11 : 16;
    const uint32_t koff = (uint32_t)((((j >> 1) & 7) << 3) | ((j & 1) << 2));
#pragma unroll
    for (int p = 0; p < 32; p++) {
        int r = p * 8 + rr;
        uint32_t soff = abase + (((uint32_t)r << 6) + (koff ^ (((uint32_t)(r & 7)) << 3))) * 4u;
        if (j < jmax) {
            cp16(soff, x + (size_t)(tile * TILE_M + r) * INSZ + c0 + 4 * j);
        } else if (ch == 4 && j == 11) {
            asm volatile("st.shared.v4.u32 [%0], {%1,%1,%1,%1};" :: "r"(soff), "r"(0u) : "memory");
        }
    }
    CP_COMMIT();
}

// ---------------- GEMM: d_xg = x @ W_ih^T  (tf32 mma.sync, persistent) ----------------
__global__ void __launch_bounds__(128, 1)
gemm_kernel(const float* __restrict__ x, const float* __restrict__ W) {
    extern __shared__ float sm[];
    float* sA0 = sm;
    float* sA1 = sm + A_ELEMS;
    float* sB  = sm + 2 * A_ELEMS;
    const uint32_t sbase = smem_u32(sm);
    const uint32_t aB[2] = { sbase, sbase + A_ELEMS * 4u };
    float* sAp[2] = { sA0, sA1 };

    const int tid  = threadIdx.x;
    const int w    = tid >> 5;
    const int lane = tid & 31;
    const int g    = lane >> 2;       // 0..7
    const int tg   = lane & 3;

    cp_chunk(x, aB[0], blockIdx.x, 0);

    // B fill (once): W[n][k] -> fragment-pair layout
    for (int i = tid; i < NG * INSZ; i += 128) {
        int n = i / INSZ, k = i - n * INSZ;
        sB[(((k >> 3) * 64 + n) << 3) + ((k & 3) << 1) + ((k & 7) >> 2)] = W[i];
    }
    for (int i = tid; i < 256; i += 128) {
        int n = i >> 2, q = i & 3;
        sB[((37 * 64 + n) << 3) + (q << 1) + 1] = 0.0f;
    }
    __syncthreads();

    int buf = 0;
    for (int tile = blockIdx.x; tile < NTILES; tile += GRID_G) {
        float acc[4][8][4];
#pragma unroll
        for (int i = 0; i < 4; i++)
#pragma unroll
            for (int j = 0; j < 8; j++)
#pragma unroll
                for (int r = 0; r < 4; r++) acc[i][j][r] = 0.0f;

        for (int ch = 0; ch < 5; ch++) {
            int ntile = tile, nch = ch + 1;
            if (nch == 5) { ntile = tile + GRID_G; nch = 0; }
            if (ntile < NTILES) cp_chunk(x, aB[buf ^ 1], ntile, nch);
            else CP_COMMIT();
            CP_WAIT1();
            __syncthreads();

            const uint32_t* A = reinterpret_cast<const uint32_t*>(sAp[buf]);
            const int ks = (ch == 4) ? 6 : 8;
            for (int s = 0; s < ks; s++) {
                uint2 bb[8];
                const uint2* Bf = reinterpret_cast<const uint2*>(
                    reinterpret_cast<const uint32_t*>(sB)
                    + ((((ch * 8 + s) * 64) + g) << 3) + (tg << 1));
#pragma unroll
                for (int j = 0; j < 8; j++) bb[j] = Bf[j * 32];
#pragma unroll
                for (int i = 0; i < 4; i++) {
                    int r0 = w * 64 + i * 16 + g;
                    uint32_t base0 = ((uint32_t)r0 << 6) + (((uint32_t)(s ^ g)) << 3);
                    uint32_t base1 = base0 + (8u << 6);
                    uint32_t a0 = A[base0 + tg];
                    uint32_t a2 = A[base0 + tg + 4];
                    uint32_t a1 = A[base1 + tg];
                    uint32_t a3 = A[base1 + tg + 4];
#pragma unroll
                    for (int j = 0; j < 8; j++)
                        mma8(acc[i][j], a0, a1, a2, a3, bb[j].x, bb[j].y);
                }
            }
            __syncthreads();
            buf ^= 1;
        }

#pragma unroll
        for (int i = 0; i < 4; i++) {
            int r0 = tile * TILE_M + w * 64 + i * 16 + g;
#pragma unroll
            for (int j = 0; j < 8; j++) {
                int col = j * 8 + tg * 2;
                *reinterpret_cast<float2*>(&d_xg[(size_t)r0 * NG + col]) =
                    make_float2(acc[i][j][0], acc[i][j][1]);
                *reinterpret_cast<float2*>(&d_xg[(size_t)(r0 + 8) * NG + col]) =
                    make_float2(acc[i][j][2], acc[i][j][3]);
            }
        }
    }
}

// ---------------- scan ----------------
__device__ __forceinline__ float sigf(float x) {
    float e = __expf(-x);
    return __fdividef(1.0f, 1.0f + e);
}
__device__ __forceinline__ float tanhapx(float x) {
    float y;
    asm("tanh.approx.f32 %0, %1;" : "=f"(y) : "f"(x));
    return y;
}

__global__ void __launch_bounds__(128)
scan_kernel(const float* __restrict__ Whh,
            const float* __restrict__ b_ih, const float* __restrict__ b_hh,
            const float* __restrict__ W1, const float* __restrict__ b1,
            const float* __restrict__ W2, const float* __restrict__ b2,
            float* __restrict__ out) {
    const int warp = threadIdx.x >> 5;
    const int lane = threadIdx.x & 31;
    const int b = blockIdx.x * 4 + warp;
    const int l = lane & 15;
    const unsigned FULL = 0xffffffffu;

    float w1r[HID], w2r[HID];
#pragma unroll
    for (int k = 0; k < HID; k++) {
        w1r[k] = Whh[lane * HID + k];
        w2r[k] = Whh[(lane + 32) * HID + k];
    }
    const float biasA = b_ih[lane] + b_hh[lane];
    const float biasB = b_ih[lane + 32] + b_hh[lane + 32];

    float h = 0.0f, c = 0.0f;
    const float* xpA = d_xg + (size_t)b * NG + lane;
    const float* xpB = xpA + 32;

    float xa0 = xpA[0 * STRIDE_T], xb0 = xpB[0 * STRIDE_T];
    float xa1 = xpA[1 * STRIDE_T], xb1 = xpB[1 * STRIDE_T];
    float xa2 = xpA[2 * STRIDE_T], xb2 = xpB[2 * STRIDE_T];
    float xa3 = xpA[3 * STRIDE_T], xb3 = xpB[3 * STRIDE_T];

#define STEP(XA, XB, PIDX)                                              \
    {                                                                   \
        float g1 = XA + biasA;                                          \
        float g2 = XB + biasB;                                          \
        XA = xpA[(size_t)(PIDX) * STRIDE_T];                            \
        XB = xpB[(size_t)(PIDX) * STRIDE_T];                            \
        float g1b = 0.0f, g2b = 0.0f;                                   \
        _Pragma("unroll")                                               \
        for (int k = 0; k < 8; k++) {                                   \
            float hk = __shfl_sync(FULL, h, k);                         \
            g1 = fmaf(hk, w1r[k], g1);                                  \
            g2 = fmaf(hk, w2r[k], g2);                                  \
        }                                                               \
        _Pragma("unroll")                                               \
        for (int k = 8; k < HID; k++) {                                 \
            float hk = __shfl_sync(FULL, h, k);                         \
            g1b = fmaf(hk, w1r[k], g1b);                                \
            g2b = fmaf(hk, w2r[k], g2b);                                \
        }                                                               \
        g1 += g1b;                                                      \
        g2 += g2b;                                                      \
        float fg = __shfl_sync(FULL, g1, l + 16);                       \
        float og = __shfl_sync(FULL, g2, l + 16);                       \
        float i_s = sigf(g1);                                           \
        float f_s = sigf(fg);                                           \
        float g_t = tanhapx(g2);                                        \
        c = fmaf(f_s, c, i_s * g_t);                                    \
        h = sigf(og) * tanhapx(c);                                      \
    }

    for (int t = 0; t < T_STEPS; t += 4) {
        const int p = t + 4;
        STEP(xa0, xb0, p + 0)
        STEP(xa1, xb1, p + 1)
        STEP(xa2, xb2, p + 2)
        STEP(xa3, xb3, p + 3)
    }
#undef STEP

    float wa[HID], wb[HID];
#pragma unroll
    for (int k = 0; k < HID; k++) {
        wa[k] = W1[lane * HID + k];
        wb[k] = W1[(lane + 32) * HID + k];
    }
    float za = b1[lane], zb = b1[lane + 32];
#pragma unroll
    for (int k = 0; k < HID; k++) {
        float hk = __shfl_sync(FULL, h, k);
        za = fmaf(hk, wa[k], za);
        zb = fmaf(hk, wb[k], zb);
    }
    za = fmaxf(za, 0.0f);
    zb = fmaxf(zb, 0.0f);
    float sacc = za * W2[lane] + zb * W2[lane + 32];
#pragma unroll
    for (int off = 16; off > 0; off >>= 1)
        sacc += __shfl_xor_sync(FULL, sacc, off);
    if (lane == 0) out[b] = 4.0f * sigf(sacc + b2[0]);
}

// ---------------- launch ----------------
extern "C" void kernel_launch(void* const* d_in, const int* in_sizes, int n_in,
                              void* d_out, int out_size) {
    const float* x    = (const float*)d_in[0];
    const float* W_ih = (const float*)d_in[1];
    const float* W_hh = (const float*)d_in[2];
    const float* b_ih = (const float*)d_in[3];
    const float* b_hh = (const float*)d_in[4];
    const float* W1   = (const float*)d_in[5];
    const float* b1   = (const float*)d_in[6];
    const float* W2   = (const float*)d_in[7];
    const float* b2   = (const float*)d_in[8];
    float* out = (float*)d_out;

    cudaFuncSetAttribute(gemm_kernel, cudaFuncAttributeMaxDynamicSharedMemorySize, SMEM_BYTES);
    gemm_kernel<<<GRID_G, 128, SMEM_BYTES>>>(x, W_ih);
    scan_kernel<<<BATCH / 4, 128>>>(W_hh, b_ih, b_hh, W1, b1, W2, b2, out);
}

// round 6
// speedup vs baseline: 6.4318x; 1.3997x over previous
#include <cuda_runtime.h>
#include <cstdint>

#define T_STEPS 512
#define BATCH   512
#define INSZ    300
#define HID     16
#define NG      64
#define NROWS   (T_STEPS*BATCH)     // 262144
#define TILE_M  256
#define NTILES  (NROWS/TILE_M)      // 1024
#define GRID_G  148
#define KSTEPS  38                  // 304/8
#define STRIDE_T (BATCH*NG)

#define A_ELEMS (TILE_M*64)
#define B_ELEMS (KSTEPS*64*8)
#define SMEM_FLOATS (2*A_ELEMS + B_ELEMS)
#define SMEM_BYTES  (SMEM_FLOATS*4) // 208896

__device__ float d_xg[(size_t)(NROWS + 4 * BATCH) * NG];

// ---------------- asm helpers ----------------
__device__ __forceinline__ uint32_t smem_u32(const void* p) {
    uint32_t a;
    asm("{ .reg .u64 t; cvta.to.shared.u64 t, %1; cvt.u32.u64 %0, t; }" : "=r"(a) : "l"(p));
    return a;
}
__device__ __forceinline__ void cp16(uint32_t sa, const float* g) {
    asm volatile("cp.async.cg.shared.global [%0], [%1], 16;" :: "r"(sa), "l"(g) : "memory");
}
#define CP_COMMIT() asm volatile("cp.async.commit_group;" ::: "memory")
#define CP_WAIT1()  asm volatile("cp.async.wait_group 1;" ::: "memory")

__device__ __forceinline__ void mma8(float* d, uint32_t a0, uint32_t a1, uint32_t a2, uint32_t a3,
                                     uint32_t b0, uint32_t b1) {
    asm volatile(
        "mma.sync.aligned.m16n8k8.row.col.f32.tf32.tf32.f32 "
        "{%0,%1,%2,%3}, {%4,%5,%6,%7}, {%8,%9}, {%0,%1,%2,%3};"
        : "+f"(d[0]), "+f"(d[1]), "+f"(d[2]), "+f"(d[3])
        : "r"(a0), "r"(a1), "r"(a2), "r"(a3), "r"(b0), "r"(b1));
}

// copy one 64-col K-chunk of a 256-row tile (256 threads)
__device__ __forceinline__ void cp_chunk(const float* __restrict__ x, uint32_t abase,
                                         int tile, int ch) {
    const int tid = threadIdx.x;
    const int j  = tid & 15;
    const int rr = tid >> 4;          // 0..15
    const int c0 = ch * 64;
    const int jmax = (ch == 4) ? 11 : 16;
    const uint32_t koff = (uint32_t)((((j >> 1) & 7) << 3) | ((j & 1) << 2));
#pragma unroll
    for (int p = 0; p < 16; p++) {
        int r = p * 16 + rr;
        uint32_t soff = abase + (((uint32_t)r << 6) + (koff ^ (((uint32_t)(r & 7)) << 3))) * 4u;
        if (j < jmax) {
            cp16(soff, x + (size_t)(tile * TILE_M + r) * INSZ + c0 + 4 * j);
        } else if (ch == 4 && j == 11) {
            asm volatile("st.shared.v4.u32 [%0], {%1,%1,%1,%1};" :: "r"(soff), "r"(0u) : "memory");
        }
    }
    CP_COMMIT();
}

// ---------------- GEMM: d_xg = x @ W_ih^T  (tf32 mma.sync, persistent, 8 warps) ----------------
__global__ void __launch_bounds__(256, 1)
gemm_kernel(const float* __restrict__ x, const float* __restrict__ W) {
    extern __shared__ float sm[];
    float* sA0 = sm;
    float* sA1 = sm + A_ELEMS;
    float* sB  = sm + 2 * A_ELEMS;
    const uint32_t sbase = smem_u32(sm);
    const uint32_t aB[2] = { sbase, sbase + A_ELEMS * 4u };
    float* sAp[2] = { sA0, sA1 };

    const int tid  = threadIdx.x;
    const int w    = tid >> 5;        // 0..7
    const int lane = tid & 31;
    const int g    = lane >> 2;
    const int tg   = lane & 3;

    cp_chunk(x, aB[0], blockIdx.x, 0);

    for (int i = tid; i < NG * INSZ; i += 256) {
        int n = i / INSZ, k = i - n * INSZ;
        sB[(((k >> 3) * 64 + n) << 3) + ((k & 3) << 1) + ((k & 7) >> 2)] = W[i];
    }
    for (int i = tid; i < 256; i += 256) {
        int n = i >> 2, q = i & 3;
        sB[((37 * 64 + n) << 3) + (q << 1) + 1] = 0.0f;
    }
    __syncthreads();

    int buf = 0;
    for (int tile = blockIdx.x; tile < NTILES; tile += GRID_G) {
        float acc[2][8][4];
#pragma unroll
        for (int i = 0; i < 2; i++)
#pragma unroll
            for (int j = 0; j < 8; j++)
#pragma unroll
                for (int r = 0; r < 4; r++) acc[i][j][r] = 0.0f;

        for (int ch = 0; ch < 5; ch++) {
            int ntile = tile, nch = ch + 1;
            if (nch == 5) { ntile = tile + GRID_G; nch = 0; }
            if (ntile < NTILES) cp_chunk(x, aB[buf ^ 1], ntile, nch);
            else CP_COMMIT();
            CP_WAIT1();
            __syncthreads();

            const uint32_t* A = reinterpret_cast<const uint32_t*>(sAp[buf]);
            const int ks = (ch == 4) ? 6 : 8;
            for (int s = 0; s < ks; s++) {
                uint2 bb[8];
                const uint2* Bf = reinterpret_cast<const uint2*>(
                    reinterpret_cast<const uint32_t*>(sB)
                    + ((((ch * 8 + s) * 64) + g) << 3) + (tg << 1));
#pragma unroll
                for (int j = 0; j < 8; j++) bb[j] = Bf[j * 32];
#pragma unroll
                for (int i = 0; i < 2; i++) {
                    int r0 = w * 32 + i * 16 + g;
                    uint32_t base0 = ((uint32_t)r0 << 6) + (((uint32_t)(s ^ g)) << 3);
                    uint32_t base1 = base0 + (8u << 6);
                    uint32_t a0 = A[base0 + tg];
                    uint32_t a2 = A[base0 + tg + 4];
                    uint32_t a1 = A[base1 + tg];
                    uint32_t a3 = A[base1 + tg + 4];
#pragma unroll
                    for (int j = 0; j < 8; j++)
                        mma8(acc[i][j], a0, a1, a2, a3, bb[j].x, bb[j].y);
                }
            }
            __syncthreads();
            buf ^= 1;
        }

#pragma unroll
        for (int i = 0; i < 2; i++) {
            int r0 = tile * TILE_M + w * 32 + i * 16 + g;
#pragma unroll
            for (int j = 0; j < 8; j++) {
                int col = j * 8 + tg * 2;
                *reinterpret_cast<float2*>(&d_xg[(size_t)r0 * NG + col]) =
                    make_float2(acc[i][j][0], acc[i][j][1]);
                *reinterpret_cast<float2*>(&d_xg[(size_t)(r0 + 8) * NG + col]) =
                    make_float2(acc[i][j][2], acc[i][j][3]);
            }
        }
    }
}

// ---------------- scan ----------------
__device__ __forceinline__ float tanhapx(float x) {
    float y;
    asm("tanh.approx.f32 %0, %1;" : "=f"(y) : "f"(x));
    return y;
}
__device__ __forceinline__ float sigt(float x) {       // sigmoid via MUFU.TANH
    return fmaf(tanhapx(0.5f * x), 0.5f, 0.5f);
}
__device__ __forceinline__ float sigx(float x) {       // exact-ish (head only)
    float e = __expf(-x);
    return __fdividef(1.0f, 1.0f + e);
}

__global__ void __launch_bounds__(128, 1)
scan_kernel(const float* __restrict__ Whh,
            const float* __restrict__ b_ih, const float* __restrict__ b_hh,
            const float* __restrict__ W1, const float* __restrict__ b1,
            const float* __restrict__ W2, const float* __restrict__ b2,
            float* __restrict__ out) {
    const int warp = threadIdx.x >> 5;
    const int lane = threadIdx.x & 31;
    const int b = blockIdx.x * 4 + warp;
    const int l = lane & 15;
    const unsigned FULL = 0xffffffffu;

    float w1r[HID], w2r[HID];
#pragma unroll
    for (int k = 0; k < HID; k++) {
        w1r[k] = Whh[lane * HID + k];
        w2r[k] = Whh[(lane + 32) * HID + k];
    }
    const float biasA = b_ih[lane] + b_hh[lane];
    const float biasB = b_ih[lane + 32] + b_hh[lane + 32];

    float h = 0.0f, c = 0.0f;
    const float* xpA = d_xg + (size_t)b * NG + lane;
    const float* xpB = xpA + 32;

    float xa0 = xpA[0 * STRIDE_T], xb0 = xpB[0 * STRIDE_T];
    float xa1 = xpA[1 * STRIDE_T], xb1 = xpB[1 * STRIDE_T];
    float xa2 = xpA[2 * STRIDE_T], xb2 = xpB[2 * STRIDE_T];
    float xa3 = xpA[3 * STRIDE_T], xb3 = xpB[3 * STRIDE_T];

#define STEP(XA, XB, PIDX)                                              \
    {                                                                   \
        float g1 = XA + biasA;                                          \
        float g2 = XB + biasB;                                          \
        XA = xpA[(size_t)(PIDX) * STRIDE_T];                            \
        XB = xpB[(size_t)(PIDX) * STRIDE_T];                            \
        float hk[HID];                                                  \
        _Pragma("unroll")                                               \
        for (int k = 0; k < HID; k++) hk[k] = __shfl_sync(FULL, h, k);  \
        float s0 = g1, s1 = 0.0f, s2 = 0.0f, s3 = 0.0f;                 \
        float r0 = g2, r1 = 0.0f, r2 = 0.0f, r3 = 0.0f;                 \
        _Pragma("unroll")                                               \
        for (int k = 0; k < HID; k += 4) {                              \
            s0 = fmaf(hk[k],     w1r[k],     s0);                       \
            s1 = fmaf(hk[k + 1], w1r[k + 1], s1);                       \
            s2 = fmaf(hk[k + 2], w1r[k + 2], s2);                       \
            s3 = fmaf(hk[k + 3], w1r[k + 3], s3);                       \
            r0 = fmaf(hk[k],     w2r[k],     r0);                       \
            r1 = fmaf(hk[k + 1], w2r[k + 1], r1);                       \
            r2 = fmaf(hk[k + 2], w2r[k + 2], r2);                       \
            r3 = fmaf(hk[k + 3], w2r[k + 3], r3);                       \
        }                                                               \
        g1 = (s0 + s1) + (s2 + s3);                                     \
        g2 = (r0 + r1) + (r2 + r3);                                     \
        float fg = __shfl_sync(FULL, g1, l + 16);                       \
        float og = __shfl_sync(FULL, g2, l + 16);                       \
        float i_s = sigt(g1);                                           \
        float f_s = sigt(fg);                                           \
        float g_t = tanhapx(g2);                                        \
        c = fmaf(f_s, c, i_s * g_t);                                    \
        h = sigt(og) * tanhapx(c);                                      \
    }

    for (int t = 0; t < T_STEPS; t += 4) {
        const int p = t + 4;
        STEP(xa0, xb0, p + 0)
        STEP(xa1, xb1, p + 1)
        STEP(xa2, xb2, p + 2)
        STEP(xa3, xb3, p + 3)
    }
#undef STEP

    float wa[HID], wb[HID];
#pragma unroll
    for (int k = 0; k < HID; k++) {
        wa[k] = W1[lane * HID + k];
        wb[k] = W1[(lane + 32) * HID + k];
    }
    float za = b1[lane], zb = b1[lane + 32];
#pragma unroll
    for (int k = 0; k < HID; k++) {
        float hk = __shfl_sync(FULL, h, k);
        za = fmaf(hk, wa[k], za);
        zb = fmaf(hk, wb[k], zb);
    }
    za = fmaxf(za, 0.0f);
    zb = fmaxf(zb, 0.0f);
    float sacc = za * W2[lane] + zb * W2[lane + 32];
#pragma unroll
    for (int off = 16; off > 0; off >>= 1)
        sacc += __shfl_xor_sync(FULL, sacc, off);
    if (lane == 0) out[b] = 4.0f * sigx(sacc + b2[0]);
}

// ---------------- launch ----------------
extern "C" void kernel_launch(void* const* d_in, const int* in_sizes, int n_in,
                              void* d_out, int out_size) {
    const float* x    = (const float*)d_in[0];
    const float* W_ih = (const float*)d_in[1];
    const float* W_hh = (const float*)d_in[2];
    const float* b_ih = (const float*)d_in[3];
    const float* b_hh = (const float*)d_in[4];
    const float* W1   = (const float*)d_in[5];
    const float* b1   = (const float*)d_in[6];
    const float* W2   = (const float*)d_in[7];
    const float* b2   = (const float*)d_in[8];
    float* out = (float*)d_out;

    cudaFuncSetAttribute(gemm_kernel, cudaFuncAttributeMaxDynamicSharedMemorySize, SMEM_BYTES);
    gemm_kernel<<<GRID_G, 256, SMEM_BYTES>>>(x, W_ih);
    scan_kernel<<<BATCH / 4, 128>>>(W_hh, b_ih, b_hh, W1, b1, W2, b2, out);
}